// round 15
// baseline (speedup 1.0000x reference)
#include <cuda_runtime.h>
#include <cuda_bf16.h>
#include <cuda_fp16.h>
#include <math.h>
#include <stdint.h>

// ---------------------------------------------------------------------------
// UnifiedZipAdapterF round 15: R12/R14 structure (best verified) with all
// epilogue/predict transcendentals switched expf -> __expf (MUFU.EX2 path,
// rel err ~5e-7, two orders below the 2.15e-4 error floor).
// Support GEMM: fp16 1-term, CTA 128x128, warp 64x32, 3 stages x 32KB, 2 CTA/SM.
// Emb/cos GEMMs: bf16 3-term, CTA 64x128, warp 32x32, 2 stages x 48KB, 2 CTA/SM.
// Softmax fused: row exp-sums in cos epilogue + light predicts pass.
// ---------------------------------------------------------------------------

#define DD        768
#define CMAX      1000
#define NPAD      1024
#define BMAX      8192
#define NSUP_PAD  100096     // ceil(100000/128)*128
#define ROWS_PAD  (BMAX + NSUP_PAD)

// ---- static device scratch (no allocations allowed) ----
__device__ __nv_bfloat16 g_Ahi[(size_t)BMAX * DD];      // emb rows bf16-hi
__device__ __nv_bfloat16 g_Alo[(size_t)BMAX * DD];      // emb rows bf16-lo
__device__ __half        g_Ah16[(size_t)NSUP_PAD * DD]; // support rows fp16
__device__ float         g_U[(size_t)BMAX * DD];        // emb-row adapter out (fp32)
__device__ __half        g_Uh[(size_t)NSUP_PAD * DD];   // support-row adapter out (fp16)
__device__ __nv_bfloat16 g_Whi[DD * DD];
__device__ __nv_bfloat16 g_Wlo[DD * DD];
__device__ __half        g_Wh16[DD * DD];
__device__ float         g_proto[CMAX * DD];
__device__ float         g_cnt[CMAX];
__device__ float         g_rowsum[BMAX];                // sum of exp(logit) per row
__device__ __nv_bfloat16 g_Ehi[(size_t)BMAX * DD];
__device__ __nv_bfloat16 g_Elo[(size_t)BMAX * DD];
__device__ __nv_bfloat16 g_Phi[(size_t)NPAD * DD];      // pad rows stay zero-init
__device__ __nv_bfloat16 g_Plo[(size_t)NPAD * DD];

// ---------------------------------------------------------------------------
__device__ __forceinline__ uint32_t s2u(const void* p) {
    uint32_t a;
    asm("{ .reg .u64 t; cvta.to.shared.u64 t, %1; cvt.u32.u64 %0, t; }"
        : "=r"(a) : "l"(p));
    return a;
}
__device__ __forceinline__ uint32_t pack2bf(float a, float b) {
    __nv_bfloat162 t = __floats2bfloat162_rn(a, b);
    return *reinterpret_cast<uint32_t*>(&t);
}
__device__ __forceinline__ uint32_t pack2h(float a, float b) {
    __half2 t = __floats2half2_rn(a, b);
    return *reinterpret_cast<uint32_t*>(&t);
}
__device__ __forceinline__ void cp16(uint32_t d, const void* s) {
    asm volatile("cp.async.cg.shared.global [%0], [%1], 16;" :: "r"(d), "l"(s));
}
__device__ __forceinline__ float silu_res(float h, float x) {
    return h / (1.f + __expf(-h)) + x;
}

#define LDSM_X4(R0, R1, R2, R3, ADDR)                                          \
    asm volatile("ldmatrix.sync.aligned.m8n8.x4.shared.b16 {%0,%1,%2,%3}, [%4];" \
        : "=r"(R0), "=r"(R1), "=r"(R2), "=r"(R3) : "r"(ADDR))
#define MMA_BF16(D, A, B)                                                      \
    asm volatile("mma.sync.aligned.m16n8k16.row.col.f32.bf16.bf16.f32 "        \
        "{%0,%1,%2,%3}, {%4,%5,%6,%7}, {%8,%9}, {%0,%1,%2,%3};"                \
        : "+f"((D)[0]), "+f"((D)[1]), "+f"((D)[2]), "+f"((D)[3])               \
        : "r"((A)[0]), "r"((A)[1]), "r"((A)[2]), "r"((A)[3]),                  \
          "r"((B)[0]), "r"((B)[1]))
#define MMA_F16(D, A, B)                                                       \
    asm volatile("mma.sync.aligned.m16n8k16.row.col.f32.f16.f16.f32 "          \
        "{%0,%1,%2,%3}, {%4,%5,%6,%7}, {%8,%9}, {%0,%1,%2,%3};"                \
        : "+f"((D)[0]), "+f"((D)[1]), "+f"((D)[2]), "+f"((D)[3])               \
        : "r"((A)[0]), "r"((A)[1]), "r"((A)[2]), "r"((A)[3]),                  \
          "r"((B)[0]), "r"((B)[1]))

// ---------------------------------------------------------------------------
// prep kernels
// ---------------------------------------------------------------------------
__global__ void zero_kernel() {
    int i = blockIdx.x * blockDim.x + threadIdx.x;
    if (i < CMAX * DD) g_proto[i] = 0.f;
    if (i < CMAX)      g_cnt[i]   = 0.f;
    if (i < BMAX)      g_rowsum[i] = 0.f;
}

__global__ void count_kernel(const int* __restrict__ lab, int N) {
    __shared__ int c[CMAX];
    int tid = threadIdx.x;
    for (int i = tid; i < CMAX; i += 256) c[i] = 0;
    __syncthreads();
    for (int i = blockIdx.x * 256 + tid; i < N; i += gridDim.x * 256)
        atomicAdd(&c[lab[i]], 1);
    __syncthreads();
    for (int i = tid; i < CMAX; i += 256)
        if (c[i]) atomicAdd(&g_cnt[i], (float)c[i]);
}

__global__ void prep_w(const float* __restrict__ W) {
    int i = blockIdx.x * blockDim.x + threadIdx.x;
    if (i < DD * DD) {
        float v = W[i];
        __nv_bfloat16 h = __float2bfloat16(v);
        g_Whi[i]  = h;
        g_Wlo[i]  = __float2bfloat16(v - __bfloat162float(h));
        g_Wh16[i] = __float2half(v);
    }
}

// emb rows -> g_Ahi/g_Alo (bf16 hi/lo); support rows (+pad) -> g_Ah16 (fp16)
__global__ void prep_x(const float* __restrict__ x, const float* __restrict__ sf,
                       int Brows, int Nrows) {
    size_t i = ((size_t)blockIdx.x * blockDim.x + threadIdx.x) * 4;
    if (i >= (size_t)ROWS_PAD * DD) return;
    size_t r = i / DD;
    if (r < (size_t)Brows) {
        float4 v = *reinterpret_cast<const float4*>(&x[i]);
        float vv[4] = {v.x, v.y, v.z, v.w};
        uint32_t hi[2], lo[2];
#pragma unroll
        for (int j = 0; j < 2; ++j) {
            float a0 = vv[2 * j], a1 = vv[2 * j + 1];
            __nv_bfloat16 h0 = __float2bfloat16(a0);
            __nv_bfloat16 h1 = __float2bfloat16(a1);
            hi[j] = pack2bf(a0, a1);
            lo[j] = pack2bf(a0 - __bfloat162float(h0), a1 - __bfloat162float(h1));
        }
        *reinterpret_cast<uint2*>(&g_Ahi[i]) = make_uint2(hi[0], hi[1]);
        *reinterpret_cast<uint2*>(&g_Alo[i]) = make_uint2(lo[0], lo[1]);
    } else {
        float4 v = make_float4(0.f, 0.f, 0.f, 0.f);
        if (r < (size_t)(Brows + Nrows))
            v = *reinterpret_cast<const float4*>(&sf[i - (size_t)Brows * DD]);
        size_t si = i - (size_t)Brows * DD;
        *reinterpret_cast<uint2*>(&g_Ah16[si]) =
            make_uint2(pack2h(v.x, v.y), pack2h(v.z, v.w));
    }
}

// ---------------------------------------------------------------------------
// GEMM cores.
// TERMS==1 (support, fp16): CTA 128x128, warp 64x32, 3 stages x 32KB, 2 CTA/SM.
// TERMS==3 (bf16 hi/lo):    CTA  64x128, warp 32x32, 2 stages x 48KB, 2 CTA/SM.
// ---------------------------------------------------------------------------
template <int TERMS>
struct Cfg {
    static const int MT    = (TERMS == 1) ? 128 : 64;
    static const int STAGE = (TERMS == 1) ? 32768 : 49152;
    static const int NS    = (TERMS == 1) ? 3 : 2;
    static const int SMEM  = NS * STAGE;                    // 96KB both
    static const int MINB  = 2;
};

template <int TERMS>
__device__ __forceinline__ void fill_part(
    const __nv_bfloat16* __restrict__ Ah, const __nv_bfloat16* __restrict__ Al,
    const __nv_bfloat16* __restrict__ Bh, const __nv_bfloat16* __restrict__ Bl,
    int arow0, int brow0, int kb, uint32_t sbase, int tid, int p)
{
    if (TERMS == 1) {
        // 1024 (tid,p) slots; each issues its A chunk AND its B chunk
        int ch = tid + p * 256;          // 0..1023
        int r = ch >> 3, c = ch & 7;
        uint32_t off = (uint32_t)(r * 128 + ((c ^ (r & 7)) << 4));
        cp16(sbase + off,          Ah + (size_t)(arow0 + r) * DD + kb + c * 8);
        cp16(sbase + 16384 + off,  Bh + (size_t)(brow0 + r) * DD + kb + c * 8);
    } else {
        // 3072 chunks: [Ahi 512][Alo 512][Bhi 1024][Blo 1024]; 3 per thread/part
#pragma unroll
        for (int k = 0; k < 3; ++k) {
            int id = p * 768 + k * 256 + tid;
            if (id < 1024) {
                int a = id & 511;
                int r = a >> 3, c = a & 7;
                uint32_t off = (uint32_t)(r * 128 + ((c ^ (r & 7)) << 4));
                const __nv_bfloat16* src = (id < 512) ? Ah : Al;
                uint32_t dst = sbase + (id < 512 ? 0u : 8192u) + off;
                cp16(dst, src + (size_t)(arow0 + r) * DD + kb + c * 8);
            } else {
                int bidx = id - 1024;
                int bsel = bidx >> 10;               // 0: Bhi, 1: Blo
                int bloc = bidx & 1023;
                int r = bloc >> 3, c = bloc & 7;
                uint32_t off = (uint32_t)(r * 128 + ((c ^ (r & 7)) << 4));
                const __nv_bfloat16* src = bsel ? Bl : Bh;
                uint32_t dst = sbase + 16384u + (bsel ? 16384u : 0u) + off;
                cp16(dst, src + (size_t)(brow0 + r) * DD + kb + c * 8);
            }
        }
    }
}

template <int TERMS>
__device__ __forceinline__ void compute_k16(uint32_t sb, int kk, int wm, int wn,
                                            int lane, float (&acc)[4][4][4])
{
    const int t = lane >> 3, li = lane & 7;
    if (TERMS == 1) {
        const uint32_t aH = sb, bH = sb + 16384;
        uint32_t ah[4][4], bh[4][2];
#pragma unroll
        for (int mi = 0; mi < 4; ++mi) {
            int r  = wm * 64 + mi * 16 + ((t & 1) << 3) + li;
            int cc = (kk << 1) + (t >> 1);
            uint32_t off = (uint32_t)(r * 128 + ((cc ^ (r & 7)) << 4));
            LDSM_X4(ah[mi][0], ah[mi][1], ah[mi][2], ah[mi][3], aH + off);
        }
#pragma unroll
        for (int p = 0; p < 2; ++p) {
            int n  = wn * 32 + p * 16 + ((t >> 1) << 3) + li;
            int cc = (kk << 1) + (t & 1);
            uint32_t off = (uint32_t)(n * 128 + ((cc ^ (n & 7)) << 4));
            LDSM_X4(bh[2 * p][0], bh[2 * p][1], bh[2 * p + 1][0], bh[2 * p + 1][1], bH + off);
        }
#pragma unroll
        for (int mi = 0; mi < 4; ++mi)
#pragma unroll
            for (int nj = 0; nj < 4; ++nj)
                MMA_F16(acc[mi][nj], ah[mi], bh[nj]);
    } else {
        const uint32_t aH = sb, aL = sb + 8192, bH = sb + 16384, bL = sb + 32768;
        uint32_t ah[2][4], al[2][4], bh[4][2], bl[4][2];
#pragma unroll
        for (int mi = 0; mi < 2; ++mi) {
            int r  = wm * 32 + mi * 16 + ((t & 1) << 3) + li;
            int cc = (kk << 1) + (t >> 1);
            uint32_t off = (uint32_t)(r * 128 + ((cc ^ (r & 7)) << 4));
            LDSM_X4(ah[mi][0], ah[mi][1], ah[mi][2], ah[mi][3], aH + off);
            LDSM_X4(al[mi][0], al[mi][1], al[mi][2], al[mi][3], aL + off);
        }
#pragma unroll
        for (int p = 0; p < 2; ++p) {
            int n  = wn * 32 + p * 16 + ((t >> 1) << 3) + li;
            int cc = (kk << 1) + (t & 1);
            uint32_t off = (uint32_t)(n * 128 + ((cc ^ (n & 7)) << 4));
            LDSM_X4(bh[2 * p][0], bh[2 * p][1], bh[2 * p + 1][0], bh[2 * p + 1][1], bH + off);
            LDSM_X4(bl[2 * p][0], bl[2 * p][1], bl[2 * p + 1][0], bl[2 * p + 1][1], bL + off);
        }
#pragma unroll
        for (int mi = 0; mi < 2; ++mi)
#pragma unroll
            for (int nj = 0; nj < 4; ++nj)
                MMA_BF16(acc[mi][nj], ah[mi], bh[nj]);
#pragma unroll
        for (int mi = 0; mi < 2; ++mi)
#pragma unroll
            for (int nj = 0; nj < 4; ++nj)
                MMA_BF16(acc[mi][nj], ah[mi], bl[nj]);
#pragma unroll
        for (int mi = 0; mi < 2; ++mi)
#pragma unroll
            for (int nj = 0; nj < 4; ++nj)
                MMA_BF16(acc[mi][nj], al[mi], bh[nj]);
    }
}

// EPI 0: adapter (bias+silu+residual -> U fp32 or fp16)
// EPI 1: cosine logits (exp(32c-32)/tau -> Lout, + row exp-sum atomics)
template <int EPI, int TERMS, bool HALF_U>
__global__ __launch_bounds__(256, Cfg<TERMS>::MINB)
void gemm_kernel(const __nv_bfloat16* __restrict__ Ah, const __nv_bfloat16* __restrict__ Al,
                 const __nv_bfloat16* __restrict__ Bh, const __nv_bfloat16* __restrict__ Bl,
                 const float* __restrict__ Xres, const float* __restrict__ bias,
                 float* __restrict__ Lout,
                 int rowEnd, int Cn)
{
    const int NS    = Cfg<TERMS>::NS;
    const int STAGE = Cfg<TERMS>::STAGE;
    const int MT    = Cfg<TERMS>::MT;
    extern __shared__ __align__(16) char smem[];
    const int tid  = threadIdx.x;
    const int lane = tid & 31, wid = tid >> 5;
    const int wm = wid >> 2, wn = wid & 3;
    const int nb0   = blockIdx.x * 128;
    const int arow0 = blockIdx.y * MT;
    const uint32_t sb = s2u(smem);

    float acc[4][4][4] = {};

#pragma unroll
    for (int s = 0; s < NS - 1; ++s) {
#pragma unroll
        for (int p = 0; p < 4; ++p)
            fill_part<TERMS>(Ah, Al, Bh, Bl, arow0, nb0, s * 64, sb + s * STAGE, tid, p);
        asm volatile("cp.async.commit_group;");
    }

#pragma unroll 1
    for (int s = 0; s < 12; ++s) {
        asm volatile("cp.async.wait_group %0;" :: "n"(Cfg<TERMS>::NS - 2));
        __syncthreads();
        const uint32_t cs = sb + (s % NS) * STAGE;
        const uint32_t fs = sb + ((s + NS - 1) % NS) * STAGE;
        const int fkb = (s + NS - 1) * 64;
        const bool df = (s + NS - 1) < 12;
#pragma unroll
        for (int kk = 0; kk < 4; ++kk) {
            if (df) fill_part<TERMS>(Ah, Al, Bh, Bl, arow0, nb0, fkb, fs, tid, kk);
            compute_k16<TERMS>(cs, kk, wm, wn, lane, acc);
        }
        asm volatile("cp.async.commit_group;");   // empty group when !df
    }
    __syncthreads();

    // ---- stage accumulators through smem: es[MT][132] ----
    float* es = reinterpret_cast<float*>(smem);
    const int MI = (TERMS == 1) ? 4 : 2;
    const int WMS = (TERMS == 1) ? 64 : 32;
#pragma unroll
    for (int mi = 0; mi < MI; ++mi)
#pragma unroll
        for (int nj = 0; nj < 4; ++nj) {
            int r0 = wm * WMS + mi * 16 + (lane >> 2);
            int c0 = wn * 32 + nj * 8 + (lane & 3) * 2;
            es[r0 * 132 + c0]           = acc[mi][nj][0];
            es[r0 * 132 + c0 + 1]       = acc[mi][nj][1];
            es[(r0 + 8) * 132 + c0]     = acc[mi][nj][2];
            es[(r0 + 8) * 132 + c0 + 1] = acc[mi][nj][3];
        }
    __syncthreads();

    // thread -> (row, 1/(256/MT) slice of 128 cols)
    const int SPL  = 256 / MT;             // 2 (MT=128) or 4 (MT=64)
    const int CW   = 128 / SPL;            // 64 or 32 cols per thread
    const int row  = tid / SPL;
    const int part = tid % SPL;
    const int arow = arow0 + row;
    const bool valid = (arow < rowEnd);
    const float* er = es + row * 132 + part * CW;

    if (EPI == 0) {
        if (valid) {
            const float* xr = Xres + (size_t)arow * DD + nb0 + part * CW;
            const float* br = bias + nb0 + part * CW;
            float*  urf = HALF_U ? nullptr
                                 : (g_U + (size_t)arow * DD + nb0 + part * CW);
            __half* urh = HALF_U ? (g_Uh + (size_t)arow * DD + nb0 + part * CW)
                                 : nullptr;
#pragma unroll 4
            for (int j = 0; j < CW; j += 4) {
                float4 v  = *reinterpret_cast<const float4*>(er + j);
                float4 bb = *reinterpret_cast<const float4*>(br + j);
                float4 xv = *reinterpret_cast<const float4*>(xr + j);
                float4 o;
                o.x = silu_res(v.x + bb.x, xv.x);
                o.y = silu_res(v.y + bb.y, xv.y);
                o.z = silu_res(v.z + bb.z, xv.z);
                o.w = silu_res(v.w + bb.w, xv.w);
                if (HALF_U) {
                    uint2 pk = make_uint2(pack2h(o.x, o.y), pack2h(o.z, o.w));
                    *reinterpret_cast<uint2*>(urh + j) = pk;
                } else {
                    *reinterpret_cast<float4*>(urf + j) = o;
                }
            }
        }
    } else {
        float esum = 0.f;
        if (valid) {
            const float invtau = 1.0f / 0.11f;
            float* lr = Lout + (size_t)arow * Cn + nb0 + part * CW;
            int cbase = nb0 + part * CW;
            if (cbase + CW <= Cn) {
#pragma unroll 4
                for (int j = 0; j < CW; ++j) {
                    float l = __expf(32.f * er[j] - 32.f) * invtau;
                    lr[j] = l;
                    esum += __expf(l);
                }
            } else {
#pragma unroll 4
                for (int j = 0; j < CW; ++j) {
                    int c = cbase + j;
                    if (c < Cn) {
                        float l = __expf(32.f * er[j] - 32.f) * invtau;
                        lr[j] = l;
                        esum += __expf(l);
                    }
                }
            }
        }
        // reduce the SPL threads of each row (adjacent lanes), one atomic/row
        esum += __shfl_xor_sync(0xffffffffu, esum, 1);
        if (SPL == 4) esum += __shfl_xor_sync(0xffffffffu, esum, 2);
        if (valid && part == 0) atomicAdd(&g_rowsum[arow], esum);
    }
}

// ---------------------------------------------------------------------------
// predicts = exp(logit) / rowsum   (logits <= 1/tau = 9.09: exp cannot overflow)
__global__ void predicts_kernel(const float* __restrict__ L,
                                float* __restrict__ P, int Cn)
{
    size_t i = ((size_t)blockIdx.x * blockDim.x + threadIdx.x) * 4;
    if (i >= (size_t)BMAX * Cn) return;
    int row = (int)(i / Cn);
    float inv = 1.f / g_rowsum[row];
    float4 l = *reinterpret_cast<const float4*>(L + i);
    float4 o;
    o.x = __expf(l.x) * inv;
    o.y = __expf(l.y) * inv;
    o.z = __expf(l.z) * inv;
    o.w = __expf(l.w) * inv;
    *reinterpret_cast<float4*>(P + i) = o;
}

// ---------------------------------------------------------------------------
// normalize emb rows of g_U -> emb (fp32) + g_Ehi/g_Elo; sq computed here.
__global__ __launch_bounds__(256)
void norm_emb(float* __restrict__ emb, int M) {
    int row  = blockIdx.x * 8 + (threadIdx.x >> 5);
    int lane = threadIdx.x & 31;
    if (row >= M) return;
    const float4* u = reinterpret_cast<const float4*>(&g_U[(size_t)row * DD]);
    float4 v[6];
    float sq = 0.f;
#pragma unroll
    for (int i = 0; i < 6; ++i) {
        v[i] = u[lane + 32 * i];
        sq += v[i].x * v[i].x + v[i].y * v[i].y + v[i].z * v[i].z + v[i].w * v[i].w;
    }
#pragma unroll
    for (int o = 16; o; o >>= 1) sq += __shfl_xor_sync(0xffffffffu, sq, o);
    float inv = 1.f / fmaxf(sqrtf(sq), 1e-12f);
    float4* of = reinterpret_cast<float4*>(&emb[(size_t)row * DD]);
    uint2*  eh = reinterpret_cast<uint2*>(&g_Ehi[(size_t)row * DD]);
    uint2*  el = reinterpret_cast<uint2*>(&g_Elo[(size_t)row * DD]);
#pragma unroll
    for (int i = 0; i < 6; ++i) {
        float4 w = v[i];
        w.x *= inv; w.y *= inv; w.z *= inv; w.w *= inv;
        of[lane + 32 * i] = w;
        __nv_bfloat16 h0 = __float2bfloat16(w.x), h1 = __float2bfloat16(w.y);
        __nv_bfloat16 h2 = __float2bfloat16(w.z), h3 = __float2bfloat16(w.w);
        eh[lane + 32 * i] = make_uint2(pack2bf(w.x, w.y), pack2bf(w.z, w.w));
        el[lane + 32 * i] = make_uint2(
            pack2bf(w.x - __bfloat162float(h0), w.y - __bfloat162float(h1)),
            pack2bf(w.z - __bfloat162float(h2), w.w - __bfloat162float(h3)));
    }
}

// normalize support rows of g_Uh (fp16), scatter-add into g_proto[label]
__global__ __launch_bounds__(256)
void norm_proto(const int* __restrict__ lab, int N) {
    int row  = blockIdx.x * 8 + (threadIdx.x >> 5);
    int lane = threadIdx.x & 31;
    if (row >= N) return;
    const uint4* u = reinterpret_cast<const uint4*>(&g_Uh[(size_t)row * DD]);
    float vv[24];
    float sq = 0.f;
#pragma unroll
    for (int i = 0; i < 3; ++i) {
        uint4 q = u[lane + 32 * i];              // 8 halves
        const uint32_t w[4] = {q.x, q.y, q.z, q.w};
#pragma unroll
        for (int j = 0; j < 4; ++j) {
            float2 f = __half22float2(*reinterpret_cast<const __half2*>(&w[j]));
            vv[i * 8 + 2 * j]     = f.x;
            vv[i * 8 + 2 * j + 1] = f.y;
            sq += f.x * f.x + f.y * f.y;
        }
    }
#pragma unroll
    for (int o = 16; o; o >>= 1) sq += __shfl_xor_sync(0xffffffffu, sq, o);
    float inv = 1.f / fmaxf(sqrtf(sq), 1e-12f);
    int lb = lab[row];
    float* dst = &g_proto[(size_t)lb * DD];
#pragma unroll
    for (int i = 0; i < 3; ++i) {
        int col = (lane + 32 * i) * 8;
#pragma unroll
        for (int t = 0; t < 2; ++t) {
            float a = vv[i * 8 + 4 * t]     * inv;
            float b = vv[i * 8 + 4 * t + 1] * inv;
            float c = vv[i * 8 + 4 * t + 2] * inv;
            float d = vv[i * 8 + 4 * t + 3] * inv;
            asm volatile("red.global.add.v4.f32 [%0], {%1,%2,%3,%4};"
                         :: "l"(dst + col + 4 * t), "f"(a), "f"(b), "f"(c), "f"(d)
                         : "memory");
        }
    }
}

// prototype sums -> normalized bf16 hi/lo (rows >= Cn stay zero-init)
__global__ void proto_norm_kernel(int Cn) {
    int c   = blockIdx.x;
    int tid = threadIdx.x;
    if (c >= Cn) return;
    const float* row = &g_proto[(size_t)c * DD];
    float ss = 0.f;
    for (int i = tid; i < DD; i += 256) { float v = row[i]; ss += v * v; }
    __shared__ float red[8];
#pragma unroll
    for (int o = 16; o; o >>= 1) ss += __shfl_xor_sync(0xffffffffu, ss, o);
    if ((tid & 31) == 0) red[tid >> 5] = ss;
    __syncthreads();
    if (tid < 8) {
        ss = red[tid];
#pragma unroll
        for (int o = 4; o; o >>= 1) ss += __shfl_xor_sync(0xffu, ss, o);
        if (tid == 0) red[0] = ss;
    }
    __syncthreads();
    float inv = (g_cnt[c] > 0.f) ? 1.f / fmaxf(sqrtf(red[0]), 1e-12f) : 0.f;
    for (int i = tid; i < DD; i += 256) {
        float v = row[i] * inv;
        __nv_bfloat16 h = __float2bfloat16(v);
        g_Phi[(size_t)c * DD + i] = h;
        g_Plo[(size_t)c * DD + i] = __float2bfloat16(v - __bfloat162float(h));
    }
}

// ---------------------------------------------------------------------------
extern "C" void kernel_launch(void* const* d_in, const int* in_sizes, int n_in,
                              void* d_out, int out_size)
{
    const float* x   = (const float*)d_in[0];
    const float* sf  = (const float*)d_in[1];
    const int*   lab = (const int*)d_in[2];
    const float* W   = (const float*)d_in[3];
    const float* b   = (const float*)d_in[4];
    (void)n_in;

    const int D = in_sizes[4];               // 768
    const int B = in_sizes[0] / D;           // 8192
    const int N = in_sizes[2];               // 100000
    const long long C =
        ((long long)out_size - (long long)B * D) / (2LL * B);   // 1000

    float* predicts = (float*)d_out;
    float* logits   = predicts + (long long)B * C;
    float* emb      = logits + (long long)B * C;

    static __nv_bfloat16 *pAhi = nullptr, *pAlo = nullptr, *pWhi = nullptr, *pWlo = nullptr;
    static __nv_bfloat16 *pEhi = nullptr, *pElo = nullptr, *pPhi = nullptr, *pPlo = nullptr;
    static __nv_bfloat16 *pAh16 = nullptr, *pWh16 = nullptr;
    static bool init = false;
    if (!init) {
        cudaGetSymbolAddress((void**)&pAhi,  g_Ahi);
        cudaGetSymbolAddress((void**)&pAlo,  g_Alo);
        cudaGetSymbolAddress((void**)&pWhi,  g_Whi);
        cudaGetSymbolAddress((void**)&pWlo,  g_Wlo);
        cudaGetSymbolAddress((void**)&pEhi,  g_Ehi);
        cudaGetSymbolAddress((void**)&pElo,  g_Elo);
        cudaGetSymbolAddress((void**)&pPhi,  g_Phi);
        cudaGetSymbolAddress((void**)&pPlo,  g_Plo);
        cudaGetSymbolAddress((void**)&pAh16, g_Ah16);   // fp16 bits, bf16* type
        cudaGetSymbolAddress((void**)&pWh16, g_Wh16);
        cudaFuncSetAttribute((const void*)gemm_kernel<0, 3, false>,
                             cudaFuncAttributeMaxDynamicSharedMemorySize, Cfg<3>::SMEM);
        cudaFuncSetAttribute((const void*)gemm_kernel<0, 1, true>,
                             cudaFuncAttributeMaxDynamicSharedMemorySize, Cfg<1>::SMEM);
        cudaFuncSetAttribute((const void*)gemm_kernel<1, 3, false>,
                             cudaFuncAttributeMaxDynamicSharedMemorySize, Cfg<3>::SMEM);
        init = true;
    }

    zero_kernel<<<(CMAX * DD + 255) / 256, 256>>>();
    prep_w<<<(DD * DD + 255) / 256, 256>>>(W);
    {
        size_t tot = ((size_t)ROWS_PAD * DD) / 4;
        prep_x<<<(int)((tot + 255) / 256), 256>>>(x, sf, B, N);
    }
    // support adapter GEMM: fp16 1-term, fp16 U, 2 CTA/SM
    {
        dim3 g(DD / 128, (N + 127) / 128);
        gemm_kernel<0, 1, true><<<g, 256, Cfg<1>::SMEM>>>(
            pAh16, nullptr, pWh16, nullptr, sf, b, nullptr, N, DD);
    }
    // emb adapter GEMM: bf16 3-term, fp32 U, M-tile 64, 2 CTA/SM
    {
        dim3 g(DD / 128, B / 64);
        gemm_kernel<0, 3, false><<<g, 256, Cfg<3>::SMEM>>>(
            pAhi, pAlo, pWhi, pWlo, x, b, nullptr, B, DD);
    }
    count_kernel<<<200, 256>>>(lab, N);
    norm_emb<<<(B + 7) / 8, 256>>>(emb, B);
    norm_proto<<<(N + 7) / 8, 256>>>(lab, N);
    proto_norm_kernel<<<(int)C, 256>>>((int)C);
    // cosine logits GEMM: bf16 3-term, M-tile 64, 2 CTA/SM, fused row exp-sums
    {
        dim3 g(NPAD / 128, B / 64);
        gemm_kernel<1, 3, false><<<g, 256, Cfg<3>::SMEM>>>(
            pEhi, pElo, pPhi, pPlo, nullptr, nullptr, logits, B, (int)C);
    }
    predicts_kernel<<<(int)(((long long)B * C / 4 + 255) / 256), 256>>>(
        logits, predicts, (int)C);
}

// round 16
// speedup vs baseline: 1.0298x; 1.0298x over previous
#include <cuda_runtime.h>
#include <cuda_bf16.h>
#include <cuda_fp16.h>
#include <math.h>
#include <stdint.h>

// ---------------------------------------------------------------------------
// UnifiedZipAdapterF round 16: R15 kernels unchanged; the emb chain
// (emb GEMM + norm_emb) forks onto a side stream concurrent with the
// support chain (support GEMM + norm_proto + proto_norm) via the
// graph-capture-legal event fork/join pattern. Join before cos GEMM.
// ---------------------------------------------------------------------------

#define DD        768
#define CMAX      1000
#define NPAD      1024
#define BMAX      8192
#define NSUP_PAD  100096     // ceil(100000/128)*128
#define ROWS_PAD  (BMAX + NSUP_PAD)

// ---- static device scratch (no allocations allowed) ----
__device__ __nv_bfloat16 g_Ahi[(size_t)BMAX * DD];      // emb rows bf16-hi
__device__ __nv_bfloat16 g_Alo[(size_t)BMAX * DD];      // emb rows bf16-lo
__device__ __half        g_Ah16[(size_t)NSUP_PAD * DD]; // support rows fp16
__device__ float         g_U[(size_t)BMAX * DD];        // emb-row adapter out (fp32)
__device__ __half        g_Uh[(size_t)NSUP_PAD * DD];   // support-row adapter out (fp16)
__device__ __nv_bfloat16 g_Whi[DD * DD];
__device__ __nv_bfloat16 g_Wlo[DD * DD];
__device__ __half        g_Wh16[DD * DD];
__device__ float         g_proto[CMAX * DD];
__device__ float         g_cnt[CMAX];
__device__ float         g_rowsum[BMAX];                // sum of exp(logit) per row
__device__ __nv_bfloat16 g_Ehi[(size_t)BMAX * DD];
__device__ __nv_bfloat16 g_Elo[(size_t)BMAX * DD];
__device__ __nv_bfloat16 g_Phi[(size_t)NPAD * DD];      // pad rows stay zero-init
__device__ __nv_bfloat16 g_Plo[(size_t)NPAD * DD];

// ---------------------------------------------------------------------------
__device__ __forceinline__ uint32_t s2u(const void* p) {
    uint32_t a;
    asm("{ .reg .u64 t; cvta.to.shared.u64 t, %1; cvt.u32.u64 %0, t; }"
        : "=r"(a) : "l"(p));
    return a;
}
__device__ __forceinline__ uint32_t pack2bf(float a, float b) {
    __nv_bfloat162 t = __floats2bfloat162_rn(a, b);
    return *reinterpret_cast<uint32_t*>(&t);
}
__device__ __forceinline__ uint32_t pack2h(float a, float b) {
    __half2 t = __floats2half2_rn(a, b);
    return *reinterpret_cast<uint32_t*>(&t);
}
__device__ __forceinline__ void cp16(uint32_t d, const void* s) {
    asm volatile("cp.async.cg.shared.global [%0], [%1], 16;" :: "r"(d), "l"(s));
}
__device__ __forceinline__ float silu_res(float h, float x) {
    return h / (1.f + __expf(-h)) + x;
}

#define LDSM_X4(R0, R1, R2, R3, ADDR)                                          \
    asm volatile("ldmatrix.sync.aligned.m8n8.x4.shared.b16 {%0,%1,%2,%3}, [%4];" \
        : "=r"(R0), "=r"(R1), "=r"(R2), "=r"(R3) : "r"(ADDR))
#define MMA_BF16(D, A, B)                                                      \
    asm volatile("mma.sync.aligned.m16n8k16.row.col.f32.bf16.bf16.f32 "        \
        "{%0,%1,%2,%3}, {%4,%5,%6,%7}, {%8,%9}, {%0,%1,%2,%3};"                \
        : "+f"((D)[0]), "+f"((D)[1]), "+f"((D)[2]), "+f"((D)[3])               \
        : "r"((A)[0]), "r"((A)[1]), "r"((A)[2]), "r"((A)[3]),                  \
          "r"((B)[0]), "r"((B)[1]))
#define MMA_F16(D, A, B)                                                       \
    asm volatile("mma.sync.aligned.m16n8k16.row.col.f32.f16.f16.f32 "          \
        "{%0,%1,%2,%3}, {%4,%5,%6,%7}, {%8,%9}, {%0,%1,%2,%3};"                \
        : "+f"((D)[0]), "+f"((D)[1]), "+f"((D)[2]), "+f"((D)[3])               \
        : "r"((A)[0]), "r"((A)[1]), "r"((A)[2]), "r"((A)[3]),                  \
          "r"((B)[0]), "r"((B)[1]))

// ---------------------------------------------------------------------------
// prep kernels
// ---------------------------------------------------------------------------
__global__ void zero_kernel() {
    int i = blockIdx.x * blockDim.x + threadIdx.x;
    if (i < CMAX * DD) g_proto[i] = 0.f;
    if (i < CMAX)      g_cnt[i]   = 0.f;
    if (i < BMAX)      g_rowsum[i] = 0.f;
}

__global__ void count_kernel(const int* __restrict__ lab, int N) {
    __shared__ int c[CMAX];
    int tid = threadIdx.x;
    for (int i = tid; i < CMAX; i += 256) c[i] = 0;
    __syncthreads();
    for (int i = blockIdx.x * 256 + tid; i < N; i += gridDim.x * 256)
        atomicAdd(&c[lab[i]], 1);
    __syncthreads();
    for (int i = tid; i < CMAX; i += 256)
        if (c[i]) atomicAdd(&g_cnt[i], (float)c[i]);
}

__global__ void prep_w(const float* __restrict__ W) {
    int i = blockIdx.x * blockDim.x + threadIdx.x;
    if (i < DD * DD) {
        float v = W[i];
        __nv_bfloat16 h = __float2bfloat16(v);
        g_Whi[i]  = h;
        g_Wlo[i]  = __float2bfloat16(v - __bfloat162float(h));
        g_Wh16[i] = __float2half(v);
    }
}

// emb rows -> g_Ahi/g_Alo (bf16 hi/lo); support rows (+pad) -> g_Ah16 (fp16)
__global__ void prep_x(const float* __restrict__ x, const float* __restrict__ sf,
                       int Brows, int Nrows) {
    size_t i = ((size_t)blockIdx.x * blockDim.x + threadIdx.x) * 4;
    if (i >= (size_t)ROWS_PAD * DD) return;
    size_t r = i / DD;
    if (r < (size_t)Brows) {
        float4 v = *reinterpret_cast<const float4*>(&x[i]);
        float vv[4] = {v.x, v.y, v.z, v.w};
        uint32_t hi[2], lo[2];
#pragma unroll
        for (int j = 0; j < 2; ++j) {
            float a0 = vv[2 * j], a1 = vv[2 * j + 1];
            __nv_bfloat16 h0 = __float2bfloat16(a0);
            __nv_bfloat16 h1 = __float2bfloat16(a1);
            hi[j] = pack2bf(a0, a1);
            lo[j] = pack2bf(a0 - __bfloat162float(h0), a1 - __bfloat162float(h1));
        }
        *reinterpret_cast<uint2*>(&g_Ahi[i]) = make_uint2(hi[0], hi[1]);
        *reinterpret_cast<uint2*>(&g_Alo[i]) = make_uint2(lo[0], lo[1]);
    } else {
        float4 v = make_float4(0.f, 0.f, 0.f, 0.f);
        if (r < (size_t)(Brows + Nrows))
            v = *reinterpret_cast<const float4*>(&sf[i - (size_t)Brows * DD]);
        size_t si = i - (size_t)Brows * DD;
        *reinterpret_cast<uint2*>(&g_Ah16[si]) =
            make_uint2(pack2h(v.x, v.y), pack2h(v.z, v.w));
    }
}

// ---------------------------------------------------------------------------
// GEMM cores.
// TERMS==1 (support, fp16): CTA 128x128, warp 64x32, 3 stages x 32KB, 2 CTA/SM.
// TERMS==3 (bf16 hi/lo):    CTA  64x128, warp 32x32, 2 stages x 48KB, 2 CTA/SM.
// ---------------------------------------------------------------------------
template <int TERMS>
struct Cfg {
    static const int MT    = (TERMS == 1) ? 128 : 64;
    static const int STAGE = (TERMS == 1) ? 32768 : 49152;
    static const int NS    = (TERMS == 1) ? 3 : 2;
    static const int SMEM  = NS * STAGE;                    // 96KB both
    static const int MINB  = 2;
};

template <int TERMS>
__device__ __forceinline__ void fill_part(
    const __nv_bfloat16* __restrict__ Ah, const __nv_bfloat16* __restrict__ Al,
    const __nv_bfloat16* __restrict__ Bh, const __nv_bfloat16* __restrict__ Bl,
    int arow0, int brow0, int kb, uint32_t sbase, int tid, int p)
{
    if (TERMS == 1) {
        // 1024 (tid,p) slots; each issues its A chunk AND its B chunk
        int ch = tid + p * 256;          // 0..1023
        int r = ch >> 3, c = ch & 7;
        uint32_t off = (uint32_t)(r * 128 + ((c ^ (r & 7)) << 4));
        cp16(sbase + off,          Ah + (size_t)(arow0 + r) * DD + kb + c * 8);
        cp16(sbase + 16384 + off,  Bh + (size_t)(brow0 + r) * DD + kb + c * 8);
    } else {
        // 3072 chunks: [Ahi 512][Alo 512][Bhi 1024][Blo 1024]; 3 per thread/part
#pragma unroll
        for (int k = 0; k < 3; ++k) {
            int id = p * 768 + k * 256 + tid;
            if (id < 1024) {
                int a = id & 511;
                int r = a >> 3, c = a & 7;
                uint32_t off = (uint32_t)(r * 128 + ((c ^ (r & 7)) << 4));
                const __nv_bfloat16* src = (id < 512) ? Ah : Al;
                uint32_t dst = sbase + (id < 512 ? 0u : 8192u) + off;
                cp16(dst, src + (size_t)(arow0 + r) * DD + kb + c * 8);
            } else {
                int bidx = id - 1024;
                int bsel = bidx >> 10;               // 0: Bhi, 1: Blo
                int bloc = bidx & 1023;
                int r = bloc >> 3, c = bloc & 7;
                uint32_t off = (uint32_t)(r * 128 + ((c ^ (r & 7)) << 4));
                const __nv_bfloat16* src = bsel ? Bl : Bh;
                uint32_t dst = sbase + 16384u + (bsel ? 16384u : 0u) + off;
                cp16(dst, src + (size_t)(brow0 + r) * DD + kb + c * 8);
            }
        }
    }
}

template <int TERMS>
__device__ __forceinline__ void compute_k16(uint32_t sb, int kk, int wm, int wn,
                                            int lane, float (&acc)[4][4][4])
{
    const int t = lane >> 3, li = lane & 7;
    if (TERMS == 1) {
        const uint32_t aH = sb, bH = sb + 16384;
        uint32_t ah[4][4], bh[4][2];
#pragma unroll
        for (int mi = 0; mi < 4; ++mi) {
            int r  = wm * 64 + mi * 16 + ((t & 1) << 3) + li;
            int cc = (kk << 1) + (t >> 1);
            uint32_t off = (uint32_t)(r * 128 + ((cc ^ (r & 7)) << 4));
            LDSM_X4(ah[mi][0], ah[mi][1], ah[mi][2], ah[mi][3], aH + off);
        }
#pragma unroll
        for (int p = 0; p < 2; ++p) {
            int n  = wn * 32 + p * 16 + ((t >> 1) << 3) + li;
            int cc = (kk << 1) + (t & 1);
            uint32_t off = (uint32_t)(n * 128 + ((cc ^ (n & 7)) << 4));
            LDSM_X4(bh[2 * p][0], bh[2 * p][1], bh[2 * p + 1][0], bh[2 * p + 1][1], bH + off);
        }
#pragma unroll
        for (int mi = 0; mi < 4; ++mi)
#pragma unroll
            for (int nj = 0; nj < 4; ++nj)
                MMA_F16(acc[mi][nj], ah[mi], bh[nj]);
    } else {
        const uint32_t aH = sb, aL = sb + 8192, bH = sb + 16384, bL = sb + 32768;
        uint32_t ah[2][4], al[2][4], bh[4][2], bl[4][2];
#pragma unroll
        for (int mi = 0; mi < 2; ++mi) {
            int r  = wm * 32 + mi * 16 + ((t & 1) << 3) + li;
            int cc = (kk << 1) + (t >> 1);
            uint32_t off = (uint32_t)(r * 128 + ((cc ^ (r & 7)) << 4));
            LDSM_X4(ah[mi][0], ah[mi][1], ah[mi][2], ah[mi][3], aH + off);
            LDSM_X4(al[mi][0], al[mi][1], al[mi][2], al[mi][3], aL + off);
        }
#pragma unroll
        for (int p = 0; p < 2; ++p) {
            int n  = wn * 32 + p * 16 + ((t >> 1) << 3) + li;
            int cc = (kk << 1) + (t & 1);
            uint32_t off = (uint32_t)(n * 128 + ((cc ^ (n & 7)) << 4));
            LDSM_X4(bh[2 * p][0], bh[2 * p][1], bh[2 * p + 1][0], bh[2 * p + 1][1], bH + off);
            LDSM_X4(bl[2 * p][0], bl[2 * p][1], bl[2 * p + 1][0], bl[2 * p + 1][1], bL + off);
        }
#pragma unroll
        for (int mi = 0; mi < 2; ++mi)
#pragma unroll
            for (int nj = 0; nj < 4; ++nj)
                MMA_BF16(acc[mi][nj], ah[mi], bh[nj]);
#pragma unroll
        for (int mi = 0; mi < 2; ++mi)
#pragma unroll
            for (int nj = 0; nj < 4; ++nj)
                MMA_BF16(acc[mi][nj], ah[mi], bl[nj]);
#pragma unroll
        for (int mi = 0; mi < 2; ++mi)
#pragma unroll
            for (int nj = 0; nj < 4; ++nj)
                MMA_BF16(acc[mi][nj], al[mi], bh[nj]);
    }
}

// EPI 0: adapter (bias+silu+residual -> U fp32 or fp16)
// EPI 1: cosine logits (exp(32c-32)/tau -> Lout, + row exp-sum atomics)
template <int EPI, int TERMS, bool HALF_U>
__global__ __launch_bounds__(256, Cfg<TERMS>::MINB)
void gemm_kernel(const __nv_bfloat16* __restrict__ Ah, const __nv_bfloat16* __restrict__ Al,
                 const __nv_bfloat16* __restrict__ Bh, const __nv_bfloat16* __restrict__ Bl,
                 const float* __restrict__ Xres, const float* __restrict__ bias,
                 float* __restrict__ Lout,
                 int rowEnd, int Cn)
{
    const int NS    = Cfg<TERMS>::NS;
    const int STAGE = Cfg<TERMS>::STAGE;
    const int MT    = Cfg<TERMS>::MT;
    extern __shared__ __align__(16) char smem[];
    const int tid  = threadIdx.x;
    const int lane = tid & 31, wid = tid >> 5;
    const int wm = wid >> 2, wn = wid & 3;
    const int nb0   = blockIdx.x * 128;
    const int arow0 = blockIdx.y * MT;
    const uint32_t sb = s2u(smem);

    float acc[4][4][4] = {};

#pragma unroll
    for (int s = 0; s < NS - 1; ++s) {
#pragma unroll
        for (int p = 0; p < 4; ++p)
            fill_part<TERMS>(Ah, Al, Bh, Bl, arow0, nb0, s * 64, sb + s * STAGE, tid, p);
        asm volatile("cp.async.commit_group;");
    }

#pragma unroll 1
    for (int s = 0; s < 12; ++s) {
        asm volatile("cp.async.wait_group %0;" :: "n"(Cfg<TERMS>::NS - 2));
        __syncthreads();
        const uint32_t cs = sb + (s % NS) * STAGE;
        const uint32_t fs = sb + ((s + NS - 1) % NS) * STAGE;
        const int fkb = (s + NS - 1) * 64;
        const bool df = (s + NS - 1) < 12;
#pragma unroll
        for (int kk = 0; kk < 4; ++kk) {
            if (df) fill_part<TERMS>(Ah, Al, Bh, Bl, arow0, nb0, fkb, fs, tid, kk);
            compute_k16<TERMS>(cs, kk, wm, wn, lane, acc);
        }
        asm volatile("cp.async.commit_group;");   // empty group when !df
    }
    __syncthreads();

    // ---- stage accumulators through smem: es[MT][132] ----
    float* es = reinterpret_cast<float*>(smem);
    const int MI = (TERMS == 1) ? 4 : 2;
    const int WMS = (TERMS == 1) ? 64 : 32;
#pragma unroll
    for (int mi = 0; mi < MI; ++mi)
#pragma unroll
        for (int nj = 0; nj < 4; ++nj) {
            int r0 = wm * WMS + mi * 16 + (lane >> 2);
            int c0 = wn * 32 + nj * 8 + (lane & 3) * 2;
            es[r0 * 132 + c0]           = acc[mi][nj][0];
            es[r0 * 132 + c0 + 1]       = acc[mi][nj][1];
            es[(r0 + 8) * 132 + c0]     = acc[mi][nj][2];
            es[(r0 + 8) * 132 + c0 + 1] = acc[mi][nj][3];
        }
    __syncthreads();

    // thread -> (row, 1/(256/MT) slice of 128 cols)
    const int SPL  = 256 / MT;             // 2 (MT=128) or 4 (MT=64)
    const int CW   = 128 / SPL;            // 64 or 32 cols per thread
    const int row  = tid / SPL;
    const int part = tid % SPL;
    const int arow = arow0 + row;
    const bool valid = (arow < rowEnd);
    const float* er = es + row * 132 + part * CW;

    if (EPI == 0) {
        if (valid) {
            const float* xr = Xres + (size_t)arow * DD + nb0 + part * CW;
            const float* br = bias + nb0 + part * CW;
            float*  urf = HALF_U ? nullptr
                                 : (g_U + (size_t)arow * DD + nb0 + part * CW);
            __half* urh = HALF_U ? (g_Uh + (size_t)arow * DD + nb0 + part * CW)
                                 : nullptr;
#pragma unroll 4
            for (int j = 0; j < CW; j += 4) {
                float4 v  = *reinterpret_cast<const float4*>(er + j);
                float4 bb = *reinterpret_cast<const float4*>(br + j);
                float4 xv = *reinterpret_cast<const float4*>(xr + j);
                float4 o;
                o.x = silu_res(v.x + bb.x, xv.x);
                o.y = silu_res(v.y + bb.y, xv.y);
                o.z = silu_res(v.z + bb.z, xv.z);
                o.w = silu_res(v.w + bb.w, xv.w);
                if (HALF_U) {
                    uint2 pk = make_uint2(pack2h(o.x, o.y), pack2h(o.z, o.w));
                    *reinterpret_cast<uint2*>(urh + j) = pk;
                } else {
                    *reinterpret_cast<float4*>(urf + j) = o;
                }
            }
        }
    } else {
        float esum = 0.f;
        if (valid) {
            const float invtau = 1.0f / 0.11f;
            float* lr = Lout + (size_t)arow * Cn + nb0 + part * CW;
            int cbase = nb0 + part * CW;
            if (cbase + CW <= Cn) {
#pragma unroll 4
                for (int j = 0; j < CW; ++j) {
                    float l = __expf(32.f * er[j] - 32.f) * invtau;
                    lr[j] = l;
                    esum += __expf(l);
                }
            } else {
#pragma unroll 4
                for (int j = 0; j < CW; ++j) {
                    int c = cbase + j;
                    if (c < Cn) {
                        float l = __expf(32.f * er[j] - 32.f) * invtau;
                        lr[j] = l;
                        esum += __expf(l);
                    }
                }
            }
        }
        // reduce the SPL threads of each row (adjacent lanes), one atomic/row
        esum += __shfl_xor_sync(0xffffffffu, esum, 1);
        if (SPL == 4) esum += __shfl_xor_sync(0xffffffffu, esum, 2);
        if (valid && part == 0) atomicAdd(&g_rowsum[arow], esum);
    }
}

// ---------------------------------------------------------------------------
// predicts = exp(logit) / rowsum   (logits <= 1/tau = 9.09: exp cannot overflow)
__global__ void predicts_kernel(const float* __restrict__ L,
                                float* __restrict__ P, int Cn)
{
    size_t i = ((size_t)blockIdx.x * blockDim.x + threadIdx.x) * 4;
    if (i >= (size_t)BMAX * Cn) return;
    int row = (int)(i / Cn);
    float inv = 1.f / g_rowsum[row];
    float4 l = *reinterpret_cast<const float4*>(L + i);
    float4 o;
    o.x = __expf(l.x) * inv;
    o.y = __expf(l.y) * inv;
    o.z = __expf(l.z) * inv;
    o.w = __expf(l.w) * inv;
    *reinterpret_cast<float4*>(P + i) = o;
}

// ---------------------------------------------------------------------------
// normalize emb rows of g_U -> emb (fp32) + g_Ehi/g_Elo; sq computed here.
__global__ __launch_bounds__(256)
void norm_emb(float* __restrict__ emb, int M) {
    int row  = blockIdx.x * 8 + (threadIdx.x >> 5);
    int lane = threadIdx.x & 31;
    if (row >= M) return;
    const float4* u = reinterpret_cast<const float4*>(&g_U[(size_t)row * DD]);
    float4 v[6];
    float sq = 0.f;
#pragma unroll
    for (int i = 0; i < 6; ++i) {
        v[i] = u[lane + 32 * i];
        sq += v[i].x * v[i].x + v[i].y * v[i].y + v[i].z * v[i].z + v[i].w * v[i].w;
    }
#pragma unroll
    for (int o = 16; o; o >>= 1) sq += __shfl_xor_sync(0xffffffffu, sq, o);
    float inv = 1.f / fmaxf(sqrtf(sq), 1e-12f);
    float4* of = reinterpret_cast<float4*>(&emb[(size_t)row * DD]);
    uint2*  eh = reinterpret_cast<uint2*>(&g_Ehi[(size_t)row * DD]);
    uint2*  el = reinterpret_cast<uint2*>(&g_Elo[(size_t)row * DD]);
#pragma unroll
    for (int i = 0; i < 6; ++i) {
        float4 w = v[i];
        w.x *= inv; w.y *= inv; w.z *= inv; w.w *= inv;
        of[lane + 32 * i] = w;
        __nv_bfloat16 h0 = __float2bfloat16(w.x), h1 = __float2bfloat16(w.y);
        __nv_bfloat16 h2 = __float2bfloat16(w.z), h3 = __float2bfloat16(w.w);
        eh[lane + 32 * i] = make_uint2(pack2bf(w.x, w.y), pack2bf(w.z, w.w));
        el[lane + 32 * i] = make_uint2(
            pack2bf(w.x - __bfloat162float(h0), w.y - __bfloat162float(h1)),
            pack2bf(w.z - __bfloat162float(h2), w.w - __bfloat162float(h3)));
    }
}

// normalize support rows of g_Uh (fp16), scatter-add into g_proto[label]
__global__ __launch_bounds__(256)
void norm_proto(const int* __restrict__ lab, int N) {
    int row  = blockIdx.x * 8 + (threadIdx.x >> 5);
    int lane = threadIdx.x & 31;
    if (row >= N) return;
    const uint4* u = reinterpret_cast<const uint4*>(&g_Uh[(size_t)row * DD]);
    float vv[24];
    float sq = 0.f;
#pragma unroll
    for (int i = 0; i < 3; ++i) {
        uint4 q = u[lane + 32 * i];              // 8 halves
        const uint32_t w[4] = {q.x, q.y, q.z, q.w};
#pragma unroll
        for (int j = 0; j < 4; ++j) {
            float2 f = __half22float2(*reinterpret_cast<const __half2*>(&w[j]));
            vv[i * 8 + 2 * j]     = f.x;
            vv[i * 8 + 2 * j + 1] = f.y;
            sq += f.x * f.x + f.y * f.y;
        }
    }
#pragma unroll
    for (int o = 16; o; o >>= 1) sq += __shfl_xor_sync(0xffffffffu, sq, o);
    float inv = 1.f / fmaxf(sqrtf(sq), 1e-12f);
    int lb = lab[row];
    float* dst = &g_proto[(size_t)lb * DD];
#pragma unroll
    for (int i = 0; i < 3; ++i) {
        int col = (lane + 32 * i) * 8;
#pragma unroll
        for (int t = 0; t < 2; ++t) {
            float a = vv[i * 8 + 4 * t]     * inv;
            float b = vv[i * 8 + 4 * t + 1] * inv;
            float c = vv[i * 8 + 4 * t + 2] * inv;
            float d = vv[i * 8 + 4 * t + 3] * inv;
            asm volatile("red.global.add.v4.f32 [%0], {%1,%2,%3,%4};"
                         :: "l"(dst + col + 4 * t), "f"(a), "f"(b), "f"(c), "f"(d)
                         : "memory");
        }
    }
}

// prototype sums -> normalized bf16 hi/lo (rows >= Cn stay zero-init)
__global__ void proto_norm_kernel(int Cn) {
    int c   = blockIdx.x;
    int tid = threadIdx.x;
    if (c >= Cn) return;
    const float* row = &g_proto[(size_t)c * DD];
    float ss = 0.f;
    for (int i = tid; i < DD; i += 256) { float v = row[i]; ss += v * v; }
    __shared__ float red[8];
#pragma unroll
    for (int o = 16; o; o >>= 1) ss += __shfl_xor_sync(0xffffffffu, ss, o);
    if ((tid & 31) == 0) red[tid >> 5] = ss;
    __syncthreads();
    if (tid < 8) {
        ss = red[tid];
#pragma unroll
        for (int o = 4; o; o >>= 1) ss += __shfl_xor_sync(0xffu, ss, o);
        if (tid == 0) red[0] = ss;
    }
    __syncthreads();
    float inv = (g_cnt[c] > 0.f) ? 1.f / fmaxf(sqrtf(red[0]), 1e-12f) : 0.f;
    for (int i = tid; i < DD; i += 256) {
        float v = row[i] * inv;
        __nv_bfloat16 h = __float2bfloat16(v);
        g_Phi[(size_t)c * DD + i] = h;
        g_Plo[(size_t)c * DD + i] = __float2bfloat16(v - __bfloat162float(h));
    }
}

// ---------------------------------------------------------------------------
extern "C" void kernel_launch(void* const* d_in, const int* in_sizes, int n_in,
                              void* d_out, int out_size)
{
    const float* x   = (const float*)d_in[0];
    const float* sf  = (const float*)d_in[1];
    const int*   lab = (const int*)d_in[2];
    const float* W   = (const float*)d_in[3];
    const float* b   = (const float*)d_in[4];
    (void)n_in;

    const int D = in_sizes[4];               // 768
    const int B = in_sizes[0] / D;           // 8192
    const int N = in_sizes[2];               // 100000
    const long long C =
        ((long long)out_size - (long long)B * D) / (2LL * B);   // 1000

    float* predicts = (float*)d_out;
    float* logits   = predicts + (long long)B * C;
    float* emb      = logits + (long long)B * C;

    static __nv_bfloat16 *pAhi = nullptr, *pAlo = nullptr, *pWhi = nullptr, *pWlo = nullptr;
    static __nv_bfloat16 *pEhi = nullptr, *pElo = nullptr, *pPhi = nullptr, *pPlo = nullptr;
    static __nv_bfloat16 *pAh16 = nullptr, *pWh16 = nullptr;
    static cudaStream_t s2 = nullptr;
    static cudaEvent_t  evFork = nullptr, evJoin = nullptr;
    static bool init = false;
    if (!init) {
        cudaGetSymbolAddress((void**)&pAhi,  g_Ahi);
        cudaGetSymbolAddress((void**)&pAlo,  g_Alo);
        cudaGetSymbolAddress((void**)&pWhi,  g_Whi);
        cudaGetSymbolAddress((void**)&pWlo,  g_Wlo);
        cudaGetSymbolAddress((void**)&pEhi,  g_Ehi);
        cudaGetSymbolAddress((void**)&pElo,  g_Elo);
        cudaGetSymbolAddress((void**)&pPhi,  g_Phi);
        cudaGetSymbolAddress((void**)&pPlo,  g_Plo);
        cudaGetSymbolAddress((void**)&pAh16, g_Ah16);   // fp16 bits, bf16* type
        cudaGetSymbolAddress((void**)&pWh16, g_Wh16);
        cudaFuncSetAttribute((const void*)gemm_kernel<0, 3, false>,
                             cudaFuncAttributeMaxDynamicSharedMemorySize, Cfg<3>::SMEM);
        cudaFuncSetAttribute((const void*)gemm_kernel<0, 1, true>,
                             cudaFuncAttributeMaxDynamicSharedMemorySize, Cfg<1>::SMEM);
        cudaFuncSetAttribute((const void*)gemm_kernel<1, 3, false>,
                             cudaFuncAttributeMaxDynamicSharedMemorySize, Cfg<3>::SMEM);
        cudaStreamCreateWithFlags(&s2, cudaStreamNonBlocking);
        cudaEventCreateWithFlags(&evFork, cudaEventDisableTiming);
        cudaEventCreateWithFlags(&evJoin, cudaEventDisableTiming);
        init = true;
    }

    // serial prologue on the capture (default) stream
    zero_kernel<<<(CMAX * DD + 255) / 256, 256>>>();
    prep_w<<<(DD * DD + 255) / 256, 256>>>(W);
    {
        size_t tot = ((size_t)ROWS_PAD * DD) / 4;
        prep_x<<<(int)((tot + 255) / 256), 256>>>(x, sf, B, N);
    }
    count_kernel<<<200, 256>>>(lab, N);

    // fork: emb chain on s2, concurrent with the support chain on s0
    cudaEventRecord(evFork, 0);
    cudaStreamWaitEvent(s2, evFork, 0);

    // --- chain B (s2): emb adapter GEMM + norm_emb ---
    {
        dim3 g(DD / 128, B / 64);
        gemm_kernel<0, 3, false><<<g, 256, Cfg<3>::SMEM, s2>>>(
            pAhi, pAlo, pWhi, pWlo, x, b, nullptr, B, DD);
    }
    norm_emb<<<(B + 7) / 8, 256, 0, s2>>>(emb, B);
    cudaEventRecord(evJoin, s2);

    // --- chain A (s0): support GEMM + norm_proto + proto_norm ---
    {
        dim3 g(DD / 128, (N + 127) / 128);
        gemm_kernel<0, 1, true><<<g, 256, Cfg<1>::SMEM>>>(
            pAh16, nullptr, pWh16, nullptr, sf, b, nullptr, N, DD);
    }
    norm_proto<<<(N + 7) / 8, 256>>>(lab, N);
    proto_norm_kernel<<<(int)C, 256>>>((int)C);

    // join before the cos GEMM (needs g_Ehi/g_Elo from chain B)
    cudaStreamWaitEvent(0, evJoin, 0);

    // cosine logits GEMM: bf16 3-term, M-tile 64, 2 CTA/SM, fused row exp-sums
    {
        dim3 g(NPAD / 128, B / 64);
        gemm_kernel<1, 3, false><<<g, 256, Cfg<3>::SMEM>>>(
            pEhi, pElo, pPhi, pPlo, nullptr, nullptr, logits, B, (int)C);
    }
    predicts_kernel<<<(int)(((long long)B * C / 4 + 255) / 256), 256>>>(
        logits, predicts, (int)C);
}

// round 17
// speedup vs baseline: 1.1102x; 1.0781x over previous
#include <cuda_runtime.h>
#include <cuda_bf16.h>
#include <cuda_fp16.h>
#include <math.h>
#include <stdint.h>

// ---------------------------------------------------------------------------
// UnifiedZipAdapterF round 17: prototype scatter (global float atomics) is
// replaced by count -> prefix -> index-scatter -> one-CTA-per-class segmented
// reduction that also fuses proto_norm. GEMM cores unchanged from R15/R16;
// two-stream fork/join extended (count/prefix/scatter + emb chain on s2).
// ---------------------------------------------------------------------------

#define DD        768
#define CMAX      1000
#define NPAD      1024
#define BMAX      8192
#define NSUP_PAD  100096     // ceil(100000/128)*128
#define ROWS_PAD  (BMAX + NSUP_PAD)

// ---- static device scratch (no allocations allowed) ----
__device__ __nv_bfloat16 g_Ahi[(size_t)BMAX * DD];      // emb rows bf16-hi
__device__ __nv_bfloat16 g_Alo[(size_t)BMAX * DD];      // emb rows bf16-lo
__device__ __half        g_Ah16[(size_t)NSUP_PAD * DD]; // support rows fp16
__device__ float         g_U[(size_t)BMAX * DD];        // emb-row adapter out (fp32)
__device__ __half        g_Uh[(size_t)NSUP_PAD * DD];   // support-row adapter out (fp16)
__device__ __nv_bfloat16 g_Whi[DD * DD];
__device__ __nv_bfloat16 g_Wlo[DD * DD];
__device__ __half        g_Wh16[DD * DD];
__device__ int           g_cnti[CMAX];
__device__ int           g_off[CMAX + 1];
__device__ int           g_cur[CMAX];
__device__ int           g_sortidx[NSUP_PAD];
__device__ float         g_rowsum[BMAX];                // sum of exp(logit) per row
__device__ __nv_bfloat16 g_Ehi[(size_t)BMAX * DD];
__device__ __nv_bfloat16 g_Elo[(size_t)BMAX * DD];
__device__ __nv_bfloat16 g_Phi[(size_t)NPAD * DD];      // pad rows stay zero-init
__device__ __nv_bfloat16 g_Plo[(size_t)NPAD * DD];

// ---------------------------------------------------------------------------
__device__ __forceinline__ uint32_t s2u(const void* p) {
    uint32_t a;
    asm("{ .reg .u64 t; cvta.to.shared.u64 t, %1; cvt.u32.u64 %0, t; }"
        : "=r"(a) : "l"(p));
    return a;
}
__device__ __forceinline__ uint32_t pack2bf(float a, float b) {
    __nv_bfloat162 t = __floats2bfloat162_rn(a, b);
    return *reinterpret_cast<uint32_t*>(&t);
}
__device__ __forceinline__ uint32_t pack2h(float a, float b) {
    __half2 t = __floats2half2_rn(a, b);
    return *reinterpret_cast<uint32_t*>(&t);
}
__device__ __forceinline__ void cp16(uint32_t d, const void* s) {
    asm volatile("cp.async.cg.shared.global [%0], [%1], 16;" :: "r"(d), "l"(s));
}
__device__ __forceinline__ float silu_res(float h, float x) {
    return h / (1.f + __expf(-h)) + x;
}

#define LDSM_X4(R0, R1, R2, R3, ADDR)                                          \
    asm volatile("ldmatrix.sync.aligned.m8n8.x4.shared.b16 {%0,%1,%2,%3}, [%4];" \
        : "=r"(R0), "=r"(R1), "=r"(R2), "=r"(R3) : "r"(ADDR))
#define MMA_BF16(D, A, B)                                                      \
    asm volatile("mma.sync.aligned.m16n8k16.row.col.f32.bf16.bf16.f32 "        \
        "{%0,%1,%2,%3}, {%4,%5,%6,%7}, {%8,%9}, {%0,%1,%2,%3};"                \
        : "+f"((D)[0]), "+f"((D)[1]), "+f"((D)[2]), "+f"((D)[3])               \
        : "r"((A)[0]), "r"((A)[1]), "r"((A)[2]), "r"((A)[3]),                  \
          "r"((B)[0]), "r"((B)[1]))
#define MMA_F16(D, A, B)                                                       \
    asm volatile("mma.sync.aligned.m16n8k16.row.col.f32.f16.f16.f32 "          \
        "{%0,%1,%2,%3}, {%4,%5,%6,%7}, {%8,%9}, {%0,%1,%2,%3};"                \
        : "+f"((D)[0]), "+f"((D)[1]), "+f"((D)[2]), "+f"((D)[3])               \
        : "r"((A)[0]), "r"((A)[1]), "r"((A)[2]), "r"((A)[3]),                  \
          "r"((B)[0]), "r"((B)[1]))

// ---------------------------------------------------------------------------
// prep / sort kernels
// ---------------------------------------------------------------------------
__global__ void zero_kernel() {
    int i = blockIdx.x * blockDim.x + threadIdx.x;
    if (i < CMAX) g_cnti[i]   = 0;
    if (i < BMAX) g_rowsum[i] = 0.f;
}

__global__ void count_kernel(const int* __restrict__ lab, int N) {
    __shared__ int c[CMAX];
    int tid = threadIdx.x;
    for (int i = tid; i < CMAX; i += 256) c[i] = 0;
    __syncthreads();
    for (int i = blockIdx.x * 256 + tid; i < N; i += gridDim.x * 256)
        atomicAdd(&c[lab[i]], 1);
    __syncthreads();
    for (int i = tid; i < CMAX; i += 256)
        if (c[i]) atomicAdd(&g_cnti[i], c[i]);
}

// exclusive prefix of g_cnti -> g_off[0..CMAX]; zero cursors. 1 CTA, 1024 thr.
__global__ void prefix_kernel() {
    __shared__ int ps[1024];
    int tid = threadIdx.x;
    int v = (tid < CMAX) ? g_cnti[tid] : 0;
    ps[tid] = v;
    __syncthreads();
    for (int off = 1; off < 1024; off <<= 1) {
        int t = (tid >= off) ? ps[tid - off] : 0;
        __syncthreads();
        ps[tid] += t;
        __syncthreads();
    }
    if (tid == 0) g_off[0] = 0;
    if (tid < CMAX) { g_off[tid + 1] = ps[tid]; g_cur[tid] = 0; }
}

__global__ void scatter_kernel(const int* __restrict__ lab, int N) {
    int i = blockIdx.x * blockDim.x + threadIdx.x;
    if (i < N) {
        int c = lab[i];
        int pos = g_off[c] + atomicAdd(&g_cur[c], 1);
        g_sortidx[pos] = i;
    }
}

__global__ void prep_w(const float* __restrict__ W) {
    int i = blockIdx.x * blockDim.x + threadIdx.x;
    if (i < DD * DD) {
        float v = W[i];
        __nv_bfloat16 h = __float2bfloat16(v);
        g_Whi[i]  = h;
        g_Wlo[i]  = __float2bfloat16(v - __bfloat162float(h));
        g_Wh16[i] = __float2half(v);
    }
}

// emb rows -> g_Ahi/g_Alo (bf16 hi/lo); support rows (+pad) -> g_Ah16 (fp16)
__global__ void prep_x(const float* __restrict__ x, const float* __restrict__ sf,
                       int Brows, int Nrows) {
    size_t i = ((size_t)blockIdx.x * blockDim.x + threadIdx.x) * 4;
    if (i >= (size_t)ROWS_PAD * DD) return;
    size_t r = i / DD;
    if (r < (size_t)Brows) {
        float4 v = *reinterpret_cast<const float4*>(&x[i]);
        float vv[4] = {v.x, v.y, v.z, v.w};
        uint32_t hi[2], lo[2];
#pragma unroll
        for (int j = 0; j < 2; ++j) {
            float a0 = vv[2 * j], a1 = vv[2 * j + 1];
            __nv_bfloat16 h0 = __float2bfloat16(a0);
            __nv_bfloat16 h1 = __float2bfloat16(a1);
            hi[j] = pack2bf(a0, a1);
            lo[j] = pack2bf(a0 - __bfloat162float(h0), a1 - __bfloat162float(h1));
        }
        *reinterpret_cast<uint2*>(&g_Ahi[i]) = make_uint2(hi[0], hi[1]);
        *reinterpret_cast<uint2*>(&g_Alo[i]) = make_uint2(lo[0], lo[1]);
    } else {
        float4 v = make_float4(0.f, 0.f, 0.f, 0.f);
        if (r < (size_t)(Brows + Nrows))
            v = *reinterpret_cast<const float4*>(&sf[i - (size_t)Brows * DD]);
        size_t si = i - (size_t)Brows * DD;
        *reinterpret_cast<uint2*>(&g_Ah16[si]) =
            make_uint2(pack2h(v.x, v.y), pack2h(v.z, v.w));
    }
}

// ---------------------------------------------------------------------------
// GEMM cores (unchanged from R15/R16).
// TERMS==1 (support, fp16): CTA 128x128, warp 64x32, 3 stages x 32KB, 2 CTA/SM.
// TERMS==3 (bf16 hi/lo):    CTA  64x128, warp 32x32, 2 stages x 48KB, 2 CTA/SM.
// ---------------------------------------------------------------------------
template <int TERMS>
struct Cfg {
    static const int MT    = (TERMS == 1) ? 128 : 64;
    static const int STAGE = (TERMS == 1) ? 32768 : 49152;
    static const int NS    = (TERMS == 1) ? 3 : 2;
    static const int SMEM  = NS * STAGE;                    // 96KB both
    static const int MINB  = 2;
};

template <int TERMS>
__device__ __forceinline__ void fill_part(
    const __nv_bfloat16* __restrict__ Ah, const __nv_bfloat16* __restrict__ Al,
    const __nv_bfloat16* __restrict__ Bh, const __nv_bfloat16* __restrict__ Bl,
    int arow0, int brow0, int kb, uint32_t sbase, int tid, int p)
{
    if (TERMS == 1) {
        int ch = tid + p * 256;          // 0..1023
        int r = ch >> 3, c = ch & 7;
        uint32_t off = (uint32_t)(r * 128 + ((c ^ (r & 7)) << 4));
        cp16(sbase + off,          Ah + (size_t)(arow0 + r) * DD + kb + c * 8);
        cp16(sbase + 16384 + off,  Bh + (size_t)(brow0 + r) * DD + kb + c * 8);
    } else {
#pragma unroll
        for (int k = 0; k < 3; ++k) {
            int id = p * 768 + k * 256 + tid;
            if (id < 1024) {
                int a = id & 511;
                int r = a >> 3, c = a & 7;
                uint32_t off = (uint32_t)(r * 128 + ((c ^ (r & 7)) << 4));
                const __nv_bfloat16* src = (id < 512) ? Ah : Al;
                uint32_t dst = sbase + (id < 512 ? 0u : 8192u) + off;
                cp16(dst, src + (size_t)(arow0 + r) * DD + kb + c * 8);
            } else {
                int bidx = id - 1024;
                int bsel = bidx >> 10;
                int bloc = bidx & 1023;
                int r = bloc >> 3, c = bloc & 7;
                uint32_t off = (uint32_t)(r * 128 + ((c ^ (r & 7)) << 4));
                const __nv_bfloat16* src = bsel ? Bl : Bh;
                uint32_t dst = sbase + 16384u + (bsel ? 16384u : 0u) + off;
                cp16(dst, src + (size_t)(brow0 + r) * DD + kb + c * 8);
            }
        }
    }
}

template <int TERMS>
__device__ __forceinline__ void compute_k16(uint32_t sb, int kk, int wm, int wn,
                                            int lane, float (&acc)[4][4][4])
{
    const int t = lane >> 3, li = lane & 7;
    if (TERMS == 1) {
        const uint32_t aH = sb, bH = sb + 16384;
        uint32_t ah[4][4], bh[4][2];
#pragma unroll
        for (int mi = 0; mi < 4; ++mi) {
            int r  = wm * 64 + mi * 16 + ((t & 1) << 3) + li;
            int cc = (kk << 1) + (t >> 1);
            uint32_t off = (uint32_t)(r * 128 + ((cc ^ (r & 7)) << 4));
            LDSM_X4(ah[mi][0], ah[mi][1], ah[mi][2], ah[mi][3], aH + off);
        }
#pragma unroll
        for (int p = 0; p < 2; ++p) {
            int n  = wn * 32 + p * 16 + ((t >> 1) << 3) + li;
            int cc = (kk << 1) + (t & 1);
            uint32_t off = (uint32_t)(n * 128 + ((cc ^ (n & 7)) << 4));
            LDSM_X4(bh[2 * p][0], bh[2 * p][1], bh[2 * p + 1][0], bh[2 * p + 1][1], bH + off);
        }
#pragma unroll
        for (int mi = 0; mi < 4; ++mi)
#pragma unroll
            for (int nj = 0; nj < 4; ++nj)
                MMA_F16(acc[mi][nj], ah[mi], bh[nj]);
    } else {
        const uint32_t aH = sb, aL = sb + 8192, bH = sb + 16384, bL = sb + 32768;
        uint32_t ah[2][4], al[2][4], bh[4][2], bl[4][2];
#pragma unroll
        for (int mi = 0; mi < 2; ++mi) {
            int r  = wm * 32 + mi * 16 + ((t & 1) << 3) + li;
            int cc = (kk << 1) + (t >> 1);
            uint32_t off = (uint32_t)(r * 128 + ((cc ^ (r & 7)) << 4));
            LDSM_X4(ah[mi][0], ah[mi][1], ah[mi][2], ah[mi][3], aH + off);
            LDSM_X4(al[mi][0], al[mi][1], al[mi][2], al[mi][3], aL + off);
        }
#pragma unroll
        for (int p = 0; p < 2; ++p) {
            int n  = wn * 32 + p * 16 + ((t >> 1) << 3) + li;
            int cc = (kk << 1) + (t & 1);
            uint32_t off = (uint32_t)(n * 128 + ((cc ^ (n & 7)) << 4));
            LDSM_X4(bh[2 * p][0], bh[2 * p][1], bh[2 * p + 1][0], bh[2 * p + 1][1], bH + off);
            LDSM_X4(bl[2 * p][0], bl[2 * p][1], bl[2 * p + 1][0], bl[2 * p + 1][1], bL + off);
        }
#pragma unroll
        for (int mi = 0; mi < 2; ++mi)
#pragma unroll
            for (int nj = 0; nj < 4; ++nj)
                MMA_BF16(acc[mi][nj], ah[mi], bh[nj]);
#pragma unroll
        for (int mi = 0; mi < 2; ++mi)
#pragma unroll
            for (int nj = 0; nj < 4; ++nj)
                MMA_BF16(acc[mi][nj], ah[mi], bl[nj]);
#pragma unroll
        for (int mi = 0; mi < 2; ++mi)
#pragma unroll
            for (int nj = 0; nj < 4; ++nj)
                MMA_BF16(acc[mi][nj], al[mi], bh[nj]);
    }
}

// EPI 0: adapter (bias+silu+residual -> U fp32 or fp16)
// EPI 1: cosine logits (exp(32c-32)/tau -> Lout, + row exp-sum atomics)
template <int EPI, int TERMS, bool HALF_U>
__global__ __launch_bounds__(256, Cfg<TERMS>::MINB)
void gemm_kernel(const __nv_bfloat16* __restrict__ Ah, const __nv_bfloat16* __restrict__ Al,
                 const __nv_bfloat16* __restrict__ Bh, const __nv_bfloat16* __restrict__ Bl,
                 const float* __restrict__ Xres, const float* __restrict__ bias,
                 float* __restrict__ Lout,
                 int rowEnd, int Cn)
{
    const int NS    = Cfg<TERMS>::NS;
    const int STAGE = Cfg<TERMS>::STAGE;
    const int MT    = Cfg<TERMS>::MT;
    extern __shared__ __align__(16) char smem[];
    const int tid  = threadIdx.x;
    const int lane = tid & 31, wid = tid >> 5;
    const int wm = wid >> 2, wn = wid & 3;
    const int nb0   = blockIdx.x * 128;
    const int arow0 = blockIdx.y * MT;
    const uint32_t sb = s2u(smem);

    float acc[4][4][4] = {};

#pragma unroll
    for (int s = 0; s < NS - 1; ++s) {
#pragma unroll
        for (int p = 0; p < 4; ++p)
            fill_part<TERMS>(Ah, Al, Bh, Bl, arow0, nb0, s * 64, sb + s * STAGE, tid, p);
        asm volatile("cp.async.commit_group;");
    }

#pragma unroll 1
    for (int s = 0; s < 12; ++s) {
        asm volatile("cp.async.wait_group %0;" :: "n"(Cfg<TERMS>::NS - 2));
        __syncthreads();
        const uint32_t cs = sb + (s % NS) * STAGE;
        const uint32_t fs = sb + ((s + NS - 1) % NS) * STAGE;
        const int fkb = (s + NS - 1) * 64;
        const bool df = (s + NS - 1) < 12;
#pragma unroll
        for (int kk = 0; kk < 4; ++kk) {
            if (df) fill_part<TERMS>(Ah, Al, Bh, Bl, arow0, nb0, fkb, fs, tid, kk);
            compute_k16<TERMS>(cs, kk, wm, wn, lane, acc);
        }
        asm volatile("cp.async.commit_group;");   // empty group when !df
    }
    __syncthreads();

    // ---- stage accumulators through smem: es[MT][132] ----
    float* es = reinterpret_cast<float*>(smem);
    const int MI = (TERMS == 1) ? 4 : 2;
    const int WMS = (TERMS == 1) ? 64 : 32;
#pragma unroll
    for (int mi = 0; mi < MI; ++mi)
#pragma unroll
        for (int nj = 0; nj < 4; ++nj) {
            int r0 = wm * WMS + mi * 16 + (lane >> 2);
            int c0 = wn * 32 + nj * 8 + (lane & 3) * 2;
            es[r0 * 132 + c0]           = acc[mi][nj][0];
            es[r0 * 132 + c0 + 1]       = acc[mi][nj][1];
            es[(r0 + 8) * 132 + c0]     = acc[mi][nj][2];
            es[(r0 + 8) * 132 + c0 + 1] = acc[mi][nj][3];
        }
    __syncthreads();

    const int SPL  = 256 / MT;             // 2 (MT=128) or 4 (MT=64)
    const int CW   = 128 / SPL;            // 64 or 32 cols per thread
    const int row  = tid / SPL;
    const int part = tid % SPL;
    const int arow = arow0 + row;
    const bool valid = (arow < rowEnd);
    const float* er = es + row * 132 + part * CW;

    if (EPI == 0) {
        if (valid) {
            const float* xr = Xres + (size_t)arow * DD + nb0 + part * CW;
            const float* br = bias + nb0 + part * CW;
            float*  urf = HALF_U ? nullptr
                                 : (g_U + (size_t)arow * DD + nb0 + part * CW);
            __half* urh = HALF_U ? (g_Uh + (size_t)arow * DD + nb0 + part * CW)
                                 : nullptr;
#pragma unroll 4
            for (int j = 0; j < CW; j += 4) {
                float4 v  = *reinterpret_cast<const float4*>(er + j);
                float4 bb = *reinterpret_cast<const float4*>(br + j);
                float4 xv = *reinterpret_cast<const float4*>(xr + j);
                float4 o;
                o.x = silu_res(v.x + bb.x, xv.x);
                o.y = silu_res(v.y + bb.y, xv.y);
                o.z = silu_res(v.z + bb.z, xv.z);
                o.w = silu_res(v.w + bb.w, xv.w);
                if (HALF_U) {
                    uint2 pk = make_uint2(pack2h(o.x, o.y), pack2h(o.z, o.w));
                    *reinterpret_cast<uint2*>(urh + j) = pk;
                } else {
                    *reinterpret_cast<float4*>(urf + j) = o;
                }
            }
        }
    } else {
        float esum = 0.f;
        if (valid) {
            const float invtau = 1.0f / 0.11f;
            float* lr = Lout + (size_t)arow * Cn + nb0 + part * CW;
            int cbase = nb0 + part * CW;
            if (cbase + CW <= Cn) {
#pragma unroll 4
                for (int j = 0; j < CW; ++j) {
                    float l = __expf(32.f * er[j] - 32.f) * invtau;
                    lr[j] = l;
                    esum += __expf(l);
                }
            } else {
#pragma unroll 4
                for (int j = 0; j < CW; ++j) {
                    int c = cbase + j;
                    if (c < Cn) {
                        float l = __expf(32.f * er[j] - 32.f) * invtau;
                        lr[j] = l;
                        esum += __expf(l);
                    }
                }
            }
        }
        esum += __shfl_xor_sync(0xffffffffu, esum, 1);
        if (SPL == 4) esum += __shfl_xor_sync(0xffffffffu, esum, 2);
        if (valid && part == 0) atomicAdd(&g_rowsum[arow], esum);
    }
}

// ---------------------------------------------------------------------------
// predicts = exp(logit) / rowsum
__global__ void predicts_kernel(const float* __restrict__ L,
                                float* __restrict__ P, int Cn)
{
    size_t i = ((size_t)blockIdx.x * blockDim.x + threadIdx.x) * 4;
    if (i >= (size_t)BMAX * Cn) return;
    int row = (int)(i / Cn);
    float inv = 1.f / g_rowsum[row];
    float4 l = *reinterpret_cast<const float4*>(L + i);
    float4 o;
    o.x = __expf(l.x) * inv;
    o.y = __expf(l.y) * inv;
    o.z = __expf(l.z) * inv;
    o.w = __expf(l.w) * inv;
    *reinterpret_cast<float4*>(P + i) = o;
}

// ---------------------------------------------------------------------------
// normalize emb rows of g_U -> emb (fp32) + g_Ehi/g_Elo
__global__ __launch_bounds__(256)
void norm_emb(float* __restrict__ emb, int M) {
    int row  = blockIdx.x * 8 + (threadIdx.x >> 5);
    int lane = threadIdx.x & 31;
    if (row >= M) return;
    const float4* u = reinterpret_cast<const float4*>(&g_U[(size_t)row * DD]);
    float4 v[6];
    float sq = 0.f;
#pragma unroll
    for (int i = 0; i < 6; ++i) {
        v[i] = u[lane + 32 * i];
        sq += v[i].x * v[i].x + v[i].y * v[i].y + v[i].z * v[i].z + v[i].w * v[i].w;
    }
#pragma unroll
    for (int o = 16; o; o >>= 1) sq += __shfl_xor_sync(0xffffffffu, sq, o);
    float inv = 1.f / fmaxf(sqrtf(sq), 1e-12f);
    float4* of = reinterpret_cast<float4*>(&emb[(size_t)row * DD]);
    uint2*  eh = reinterpret_cast<uint2*>(&g_Ehi[(size_t)row * DD]);
    uint2*  el = reinterpret_cast<uint2*>(&g_Elo[(size_t)row * DD]);
#pragma unroll
    for (int i = 0; i < 6; ++i) {
        float4 w = v[i];
        w.x *= inv; w.y *= inv; w.z *= inv; w.w *= inv;
        of[lane + 32 * i] = w;
        __nv_bfloat16 h0 = __float2bfloat16(w.x), h1 = __float2bfloat16(w.y);
        __nv_bfloat16 h2 = __float2bfloat16(w.z), h3 = __float2bfloat16(w.w);
        eh[lane + 32 * i] = make_uint2(pack2bf(w.x, w.y), pack2bf(w.z, w.w));
        el[lane + 32 * i] = make_uint2(
            pack2bf(w.x - __bfloat162float(h0), w.y - __bfloat162float(h1)),
            pack2bf(w.z - __bfloat162float(h2), w.w - __bfloat162float(h3)));
    }
}

// ---------------------------------------------------------------------------
// one CTA per class: gather sorted rows of g_Uh, row-normalize, sum (fp32),
// class-l2norm, write g_Phi/g_Plo. Replaces norm_proto + proto_norm.
__global__ __launch_bounds__(256)
void class_proto_kernel() {
    const int c = blockIdx.x;
    const int start = g_off[c], end = g_off[c + 1];
    const int tid = threadIdx.x, wid = tid >> 5, lane = tid & 31;

    float acc[24];
#pragma unroll
    for (int k = 0; k < 24; ++k) acc[k] = 0.f;

    for (int j = start + wid; j < end; j += 8) {
        int idx = g_sortidx[j];
        const uint4* u =
            reinterpret_cast<const uint4*>(g_Uh + (size_t)idx * DD) + lane * 3;
        float v[24];
        float sq = 0.f;
#pragma unroll
        for (int t = 0; t < 3; ++t) {
            uint4 q = u[t];
            uint32_t w[4] = {q.x, q.y, q.z, q.w};
#pragma unroll
            for (int m = 0; m < 4; ++m) {
                float2 f = __half22float2(*reinterpret_cast<const __half2*>(&w[m]));
                v[t * 8 + 2 * m]     = f.x;
                v[t * 8 + 2 * m + 1] = f.y;
                sq += f.x * f.x + f.y * f.y;
            }
        }
#pragma unroll
        for (int o = 16; o; o >>= 1) sq += __shfl_xor_sync(0xffffffffu, sq, o);
        float inv = 1.f / fmaxf(sqrtf(sq), 1e-12f);
#pragma unroll
        for (int k = 0; k < 24; ++k) acc[k] += v[k] * inv;
    }

    __shared__ float sacc[8][DD];   // 24KB
#pragma unroll
    for (int k = 0; k < 24; ++k) sacc[wid][lane * 24 + k] = acc[k];
    __syncthreads();

    // column sums: thread t owns cols 3t..3t+2
    const int c0 = tid * 3;
    float s0 = 0.f, s1 = 0.f, s2 = 0.f;
#pragma unroll
    for (int w = 0; w < 8; ++w) {
        s0 += sacc[w][c0];
        s1 += sacc[w][c0 + 1];
        s2 += sacc[w][c0 + 2];
    }
    float ssq = s0 * s0 + s1 * s1 + s2 * s2;
    __shared__ float red[8];
#pragma unroll
    for (int o = 16; o; o >>= 1) ssq += __shfl_xor_sync(0xffffffffu, ssq, o);
    if (lane == 0) red[wid] = ssq;
    __syncthreads();
    if (tid < 8) {
        float t = red[tid];
#pragma unroll
        for (int o = 4; o; o >>= 1) t += __shfl_xor_sync(0xffu, t, o);
        if (tid == 0) red[0] = t;
    }
    __syncthreads();
    float inv2 = (end > start) ? 1.f / fmaxf(sqrtf(red[0]), 1e-12f) : 0.f;

    float p0 = s0 * inv2, p1 = s1 * inv2, p2 = s2 * inv2;
    __nv_bfloat16 h0 = __float2bfloat16(p0);
    __nv_bfloat16 h1 = __float2bfloat16(p1);
    __nv_bfloat16 h2 = __float2bfloat16(p2);
    size_t base = (size_t)c * DD + c0;
    g_Phi[base]     = h0;
    g_Phi[base + 1] = h1;
    g_Phi[base + 2] = h2;
    g_Plo[base]     = __float2bfloat16(p0 - __bfloat162float(h0));
    g_Plo[base + 1] = __float2bfloat16(p1 - __bfloat162float(h1));
    g_Plo[base + 2] = __float2bfloat16(p2 - __bfloat162float(h2));
}

// ---------------------------------------------------------------------------
extern "C" void kernel_launch(void* const* d_in, const int* in_sizes, int n_in,
                              void* d_out, int out_size)
{
    const float* x   = (const float*)d_in[0];
    const float* sf  = (const float*)d_in[1];
    const int*   lab = (const int*)d_in[2];
    const float* W   = (const float*)d_in[3];
    const float* b   = (const float*)d_in[4];
    (void)n_in;

    const int D = in_sizes[4];               // 768
    const int B = in_sizes[0] / D;           // 8192
    const int N = in_sizes[2];               // 100000
    const long long C =
        ((long long)out_size - (long long)B * D) / (2LL * B);   // 1000

    float* predicts = (float*)d_out;
    float* logits   = predicts + (long long)B * C;
    float* emb      = logits + (long long)B * C;

    static __nv_bfloat16 *pAhi = nullptr, *pAlo = nullptr, *pWhi = nullptr, *pWlo = nullptr;
    static __nv_bfloat16 *pEhi = nullptr, *pElo = nullptr, *pPhi = nullptr, *pPlo = nullptr;
    static __nv_bfloat16 *pAh16 = nullptr, *pWh16 = nullptr;
    static cudaStream_t s2 = nullptr;
    static cudaEvent_t evZ = nullptr, evX = nullptr, evB1 = nullptr, evB2 = nullptr;
    static bool init = false;
    if (!init) {
        cudaGetSymbolAddress((void**)&pAhi,  g_Ahi);
        cudaGetSymbolAddress((void**)&pAlo,  g_Alo);
        cudaGetSymbolAddress((void**)&pWhi,  g_Whi);
        cudaGetSymbolAddress((void**)&pWlo,  g_Wlo);
        cudaGetSymbolAddress((void**)&pEhi,  g_Ehi);
        cudaGetSymbolAddress((void**)&pElo,  g_Elo);
        cudaGetSymbolAddress((void**)&pPhi,  g_Phi);
        cudaGetSymbolAddress((void**)&pPlo,  g_Plo);
        cudaGetSymbolAddress((void**)&pAh16, g_Ah16);   // fp16 bits, bf16* type
        cudaGetSymbolAddress((void**)&pWh16, g_Wh16);
        cudaFuncSetAttribute((const void*)gemm_kernel<0, 3, false>,
                             cudaFuncAttributeMaxDynamicSharedMemorySize, Cfg<3>::SMEM);
        cudaFuncSetAttribute((const void*)gemm_kernel<0, 1, true>,
                             cudaFuncAttributeMaxDynamicSharedMemorySize, Cfg<1>::SMEM);
        cudaFuncSetAttribute((const void*)gemm_kernel<1, 3, false>,
                             cudaFuncAttributeMaxDynamicSharedMemorySize, Cfg<3>::SMEM);
        cudaStreamCreateWithFlags(&s2, cudaStreamNonBlocking);
        cudaEventCreateWithFlags(&evZ,  cudaEventDisableTiming);
        cudaEventCreateWithFlags(&evX,  cudaEventDisableTiming);
        cudaEventCreateWithFlags(&evB1, cudaEventDisableTiming);
        cudaEventCreateWithFlags(&evB2, cudaEventDisableTiming);
        init = true;
    }

    // s0 prologue
    zero_kernel<<<(BMAX + 255) / 256, 256>>>();
    cudaEventRecord(evZ, 0);
    cudaStreamWaitEvent(s2, evZ, 0);

    prep_w<<<(DD * DD + 255) / 256, 256>>>(W);
    {
        size_t tot = ((size_t)ROWS_PAD * DD) / 4;
        prep_x<<<(int)((tot + 255) / 256), 256>>>(x, sf, B, N);
    }
    cudaEventRecord(evX, 0);

    // --- s2: count -> prefix -> scatter, then emb chain ---
    count_kernel<<<200, 256, 0, s2>>>(lab, N);
    prefix_kernel<<<1, 1024, 0, s2>>>();
    scatter_kernel<<<(N + 255) / 256, 256, 0, s2>>>(lab, N);
    cudaEventRecord(evB1, s2);
    cudaStreamWaitEvent(s2, evX, 0);
    {
        dim3 g(DD / 128, B / 64);
        gemm_kernel<0, 3, false><<<g, 256, Cfg<3>::SMEM, s2>>>(
            pAhi, pAlo, pWhi, pWlo, x, b, nullptr, B, DD);
    }
    norm_emb<<<(B + 7) / 8, 256, 0, s2>>>(emb, B);
    cudaEventRecord(evB2, s2);

    // --- s0: support GEMM -> class prototypes ---
    {
        dim3 g(DD / 128, (N + 127) / 128);
        gemm_kernel<0, 1, true><<<g, 256, Cfg<1>::SMEM>>>(
            pAh16, nullptr, pWh16, nullptr, sf, b, nullptr, N, DD);
    }
    cudaStreamWaitEvent(0, evB1, 0);
    class_proto_kernel<<<(int)C, 256>>>();

    // join emb chain, then cos GEMM + predicts
    cudaStreamWaitEvent(0, evB2, 0);
    {
        dim3 g(NPAD / 128, B / 64);
        gemm_kernel<1, 3, false><<<g, 256, Cfg<3>::SMEM>>>(
            pEhi, pElo, pPhi, pPlo, nullptr, nullptr, logits, B, (int)C);
    }
    predicts_kernel<<<(int)(((long long)B * C / 4 + 255) / 256), 256>>>(
        logits, predicts, (int)C);
}